// round 14
// baseline (speedup 1.0000x reference)
#include <cuda_runtime.h>
#include <cstdint>

// Problem constants
#define E_LEN  512
#define NFEA   8
#define NCLS   14
#define BATCH  8192
#define ROW    (E_LEN * NFEA)        // 4096 floats per sample
#define NPAIR  (NCLS * NCLS)         // 196

#define NBLK   304                   // 2 CTAs per SM x 152 SMs
#define TPB    512                   // 16 warps/CTA, 32 warps/SM
#define WPB    (TPB / 32)
#define NWARPS (NBLK * WPB)          // 4864

typedef unsigned long long u64;

__device__ float    g_block[NBLK];
__device__ unsigned g_count = 0;

// ---- f32x2 helpers (ptxas never auto-emits FFMA2 from C++) ----
__device__ __forceinline__ u64 pk2(float lo, float hi) {
    u64 r; asm("mov.b64 %0, {%1, %2};" : "=l"(r) : "f"(lo), "f"(hi)); return r;
}
__device__ __forceinline__ void up2(float& lo, float& hi, u64 v) {
    asm("mov.b64 {%0, %1}, %2;" : "=f"(lo), "=f"(hi) : "l"(v));
}
__device__ __forceinline__ u64 bc2(float v) {
    u64 r; asm("mov.b64 %0, {%1, %1};" : "=l"(r) : "f"(v)); return r;
}
__device__ __forceinline__ u64 fma2(u64 a, u64 b, u64 c) {
    u64 d; asm("fma.rn.f32x2 %0, %1, %2, %3;" : "=l"(d) : "l"(a), "l"(b), "l"(c)); return d;
}
__device__ __forceinline__ u64 add2(u64 a, u64 b) {
    u64 d; asm("add.rn.f32x2 %0, %1, %2;" : "=l"(d) : "l"(a), "l"(b)); return d;
}

__device__ __forceinline__ float softplus_f(float v) {
    return fmaxf(v, 0.f) + log1pf(__expf(-fabsf(v)));
}

// Partitioned halving reduction among the 8 lanes sharing (lane & 3),
// participating bits: masks 16, 8, 4.
template<int H, int W>
__device__ __forceinline__ void red_stage(u64* v, int lane) {
    const bool up = (lane & W) != 0;
    #pragma unroll
    for (int i = 0; i < H; i++) {
        u64 send = up ? v[i] : v[i + H];
        u64 recv = __shfl_xor_sync(0xffffffffu, send, W);
        u64 keep = up ? v[i + H] : v[i];
        v[i] = add2(keep, recv);
    }
}

// ---------- Single fused kernel: gram prologue + loss + grid reduction ----------
__global__ __launch_bounds__(TPB, 2)
void main_kernel(const float* __restrict__ x, const int* __restrict__ y,
                 const float* __restrict__ w, float* __restrict__ out) {
    // w packed cc-major (conflict-free): s_w[cc*512 + e] = (w[e][2cc], w[e][2cc+1])
    __shared__ u64   s_w[7 * E_LEN];           // 28 KB
    __shared__ u64   s_red[WPB][64];           // 8 KB
    __shared__ float s_dot[WPB][NCLS];
    __shared__ float s_G[NPAIR];
    __shared__ float s_wsum[WPB];
    __shared__ int   s_last;

    const int tid = threadIdx.x;
    const int lane = tid & 31, wid = tid >> 5;

    for (int idx = tid; idx < 7 * E_LEN; idx += TPB) {
        int e  = idx & (E_LEN - 1);
        int cc = idx >> 9;
        float2 wv = *(const float2*)(w + e * NCLS + 2 * cc);  // even class -> 8B aligned
        s_w[cc * E_LEN + e] = pk2(wv.x, wv.y);
    }
    __syncthreads();

    // --- Gram prologue: 105 unique pairs, warp-per-pair ---
    {
        const float* wf = (const float*)s_w;   // w[e][c] at (c>>1)*1024 + 2e + (c&1)
        for (int p = wid; p < 105; p += WPB) {
            int c1 = 0, rem = p;
            while (rem >= NCLS - c1) { rem -= NCLS - c1; c1++; }
            int c2 = c1 + rem;
            int o1 = (c1 >> 1) * 1024 + (c1 & 1);
            int o2 = (c2 >> 1) * 1024 + (c2 & 1);
            float s = 0.f;
            #pragma unroll
            for (int k = 0; k < 16; k++) {
                int e2 = 2 * (lane + 32 * k);
                s = fmaf(wf[o1 + e2], wf[o2 + e2], s);
            }
            #pragma unroll
            for (int o = 16; o; o >>= 1) s += __shfl_xor_sync(~0u, s, o);
            if (lane == 0) { s_G[c1 * NCLS + c2] = s; s_G[c2 * NCLS + c1] = s; }
        }
    }
    __syncthreads();

    // --- Main loop: warp per sample; quads of lanes share e, lane owns m-pair ---
    // e = 8*j + (lane>>2); m = 2*(lane&3), 2*(lane&3)+1
    const int gw = wid * NBLK + blockIdx.x;
    float wacc = 0.f;

    for (int s = gw; s < BATCH; s += NWARPS) {
        const float2* px = (const float2*)(x + (size_t)s * ROW);

        // depth-3 software pipeline; lane l reads float2 index 32*j + l (coalesced)
        float2 c0 = __ldcs(px + lane);
        float2 c1 = __ldcs(px + 32 + lane);
        float2 c2 = __ldcs(px + 64 + lane);

        u64 v[16];                               // f = mloc*8 + cc (cc<7; 7,15 pad)
        #pragma unroll
        for (int f = 0; f < 16; f++) v[f] = 0ull;
        float l1 = 0.f;

        #pragma unroll 8
        for (int j = 0; j < 64; j++) {
            int jn = (j + 3 < 64) ? (j + 3) : 63;
            float2 c3 = __ldcs(px + 32 * jn + lane);
            const int e = 8 * j + (lane >> 2);

            u64 b0 = bc2(c0.x), b1 = bc2(c0.y);
            #pragma unroll
            for (int cc = 0; cc < 7; cc++) {
                u64 wv = s_w[cc * E_LEN + e];
                v[cc]     = fma2(b0, wv, v[cc]);
                v[8 + cc] = fma2(b1, wv, v[8 + cc]);
            }

            // per-(b,e) variance over 8 m: quad-sum packed (sum, sumsq)
            float p1 = c0.x + c0.y;
            float p2 = fmaf(c0.x, c0.x, c0.y * c0.y);
            u64 pk = pk2(p1, p2);
            pk = add2(pk, __shfl_xor_sync(~0u, pk, 1));
            pk = add2(pk, __shfl_xor_sync(~0u, pk, 2));
            float s1, s2; up2(s1, s2, pk);
            float var = (s2 - s1 * s1 * 0.125f) * (1.0f / 7.0f);
            l1 += fabsf(var);                    // all 4 quad lanes count -> x0.25 later

            c0 = c1; c1 = c2; c2 = c3;
        }

        // reduce 16 packed partials over the 8 lanes sharing (lane&3)
        red_stage<8, 16>(v, lane);
        red_stage<4,  8>(v, lane);
        red_stage<2,  4>(v, lane);
        {
            int g = lane & 3;
            int chunk = (((lane >> 4) & 1) << 2) | (((lane >> 3) & 1) << 1) | ((lane >> 2) & 1);
            s_red[wid][g * 16 + 2 * chunk]     = v[0];
            s_red[wid][g * 16 + 2 * chunk + 1] = v[1];
        }
        __syncwarp();

        // dot[c] = max over m;  slot(g=m>>1, mloc=m&1, cc, hf): float idx = (g*16+mloc*8+cc)*2+hf
        if (lane < NCLS) {
            const float* rp = (const float*)&s_red[wid][0];
            int cc = lane >> 1, hf = lane & 1;
            float mx = -3.4e38f;
            #pragma unroll
            for (int m = 0; m < 8; m++) {
                int g = m >> 1, ml = m & 1;
                mx = fmaxf(mx, rp[(g * 16 + ml * 8 + cc) * 2 + hf]);
            }
            s_dot[wid][lane] = mx;
        }
        int yv = (lane < NCLS) ? __ldg(y + (size_t)s * NCLS + lane) : 0;
        unsigned mask = __ballot_sync(~0u, yv == 1);
        __syncwarp();

        // pairwise softplus + Gram sums, distributed over lanes
        float psum = 0.f, gs = 0.f, ds = 0.f;
        for (int idx = lane; idx < NPAIR; idx += 32) {
            int p = idx / NCLS, n = idx - p * NCLS;
            bool pp = (mask >> p) & 1, pn = (mask >> n) & 1;
            if (pp && !pn) psum += softplus_f(s_dot[wid][n] - s_dot[wid][p]);
            if (pp && pn) { float g = s_G[idx]; gs += g; if (p == n) ds += g; }
        }
        float li = l1;
        #pragma unroll
        for (int o = 16; o; o >>= 1) {
            psum += __shfl_xor_sync(~0u, psum, o);
            gs   += __shfl_xor_sync(~0u, gs,   o);
            ds   += __shfl_xor_sync(~0u, ds,   o);
            li   += __shfl_xor_sync(~0u, li,   o);
        }

        if (lane == 0) {
            float npos = (float)__popc(mask);
            float S = psum;
            if ((mask & 0x3FFFu) == 0x3FFFu) {   // nneg == 0 edge case
                S = 0.f;
                for (int c = 0; c < NCLS; c++) S += softplus_f(-s_dot[wid][c]);
            }
            float base = S / npos;
            float tv = (npos > 1.5f) ? (ds - gs / npos) / (npos - 1.f) : 0.f;
            float loss = 2.f * (0.7f * (1.f + tv) * base + 0.3f * (0.25f * li));
            wacc += loss;
        }
    }

    // --- block-local then grid reduction (deterministic fixed-order sums) ---
    if (lane == 0) s_wsum[wid] = wacc;
    __syncthreads();
    if (tid == 0) {
        float b = 0.f;
        #pragma unroll
        for (int i = 0; i < WPB; i++) b += s_wsum[i];
        g_block[blockIdx.x] = b;
        __threadfence();
        unsigned t = atomicAdd(&g_count, 1);
        s_last = (t == NBLK - 1);
    }
    __syncthreads();
    if (s_last && wid == 0) {
        __threadfence();
        float t = 0.f;
        for (int i = lane; i < NBLK; i += 32) {
            float bv; asm volatile("ld.global.cg.f32 %0, [%1];" : "=f"(bv) : "l"(g_block + i));
            t += bv;
        }
        #pragma unroll
        for (int o = 16; o; o >>= 1) t += __shfl_xor_sync(~0u, t, o);
        if (lane == 0) {
            out[0] = t * (1.0f / (float)BATCH);
            g_count = 0;                         // reset for next graph replay
        }
    }
}

extern "C" void kernel_launch(void* const* d_in, const int* in_sizes, int n_in,
                              void* d_out, int out_size) {
    const float* x = nullptr; const int* y = nullptr; const float* w = nullptr;
    for (int i = 0; i < n_in; i++) {
        if      (in_sizes[i] == BATCH * ROW)   x = (const float*)d_in[i];
        else if (in_sizes[i] == BATCH * NCLS)  y = (const int*)d_in[i];
        else if (in_sizes[i] == E_LEN * NCLS)  w = (const float*)d_in[i];
    }
    main_kernel<<<NBLK, TPB>>>(x, y, w, (float*)d_out);
}

// round 15
// speedup vs baseline: 1.2478x; 1.2478x over previous
#include <cuda_runtime.h>
#include <cstdint>

// Problem constants
#define E_LEN  512
#define NFEA   8
#define NCLS   14
#define BATCH  8192
#define ROW    (E_LEN * NFEA)        // 4096 floats per sample
#define NPAIR  (NCLS * NCLS)         // 196

#define GRID   152                   // 1 CTA per SM
#define TPB    256                   // 8 warps (high regs/thread, R1-style)
#define WPB    (TPB / 32)
#define NWARPS (GRID * WPB)          // 1216
#define WSTR   10                    // u64 per e-row of packed w (80B: 16B-aligned, conflict-free for consecutive e)

typedef unsigned long long u64;

__device__ float    g_block[GRID];
__device__ unsigned g_count = 0;

// ---- f32x2 helpers (ptxas never auto-emits packed f32x2 from C++) ----
__device__ __forceinline__ u64 pk2(float lo, float hi) {
    u64 r; asm("mov.b64 %0, {%1, %2};" : "=l"(r) : "f"(lo), "f"(hi)); return r;
}
__device__ __forceinline__ void up2(float& lo, float& hi, u64 v) {
    asm("mov.b64 {%0, %1}, %2;" : "=f"(lo), "=f"(hi) : "l"(v));
}
__device__ __forceinline__ u64 bc2(float v) {
    u64 r; asm("mov.b64 %0, {%1, %1};" : "=l"(r) : "f"(v)); return r;
}
__device__ __forceinline__ u64 fma2(u64 a, u64 b, u64 c) {
    u64 d; asm("fma.rn.f32x2 %0, %1, %2, %3;" : "=l"(d) : "l"(a), "l"(b), "l"(c)); return d;
}
__device__ __forceinline__ u64 add2(u64 a, u64 b) {
    u64 d; asm("add.rn.f32x2 %0, %1, %2;" : "=l"(d) : "l"(a), "l"(b)); return d;
}
__device__ __forceinline__ u64 mul2(u64 a, u64 b) {
    u64 d; asm("mul.rn.f32x2 %0, %1, %2;" : "=l"(d) : "l"(a), "l"(b)); return d;
}

__device__ __forceinline__ float softplus_f(float v) {
    return fmaxf(v, 0.f) + log1pf(__expf(-fabsf(v)));
}

// Partitioned halving reduction over the whole warp (R1-proven).
// After stages (32,16)(16,8)(8,4)(4,2)(2,1): lane l holds flat sums {2l, 2l+1}.
template<int H, int W>
__device__ __forceinline__ void red_stage(u64* v, int lane) {
    const bool up = (lane & W) != 0;
    #pragma unroll
    for (int i = 0; i < H; i++) {
        u64 send = up ? v[i] : v[i + H];
        u64 recv = __shfl_xor_sync(0xffffffffu, send, W);
        u64 keep = up ? v[i + H] : v[i];
        v[i] = add2(keep, recv);
    }
}

// ---------- Single fused kernel: gram prologue + loss + grid reduction ----------
__global__ __launch_bounds__(TPB, 1)
void main_kernel(const float* __restrict__ x, const int* __restrict__ y,
                 const float* __restrict__ w, float* __restrict__ out) {
    // w packed e-major: s_w[e*WSTR + k] = (w[e][2k], w[e][2k+1]), k < 7.
    // Lane-consecutive e at 80B stride: 20 words -> banks {0,20,8,28,16,4,24,12} pattern,
    // at worst 4-way for LDS.128 across 32 lanes (bandwidth-floor anyway).
    __shared__ u64   s_w[E_LEN * WSTR];        // 40 KB
    __shared__ u64   s_red[WPB][64];           // 4 KB
    __shared__ float s_dot[WPB][NCLS];
    __shared__ float s_G[NPAIR];
    __shared__ float s_wsum[WPB];
    __shared__ int   s_last;

    const int tid = threadIdx.x;
    const int lane = tid & 31, wid = tid >> 5;

    for (int idx = tid; idx < 7 * E_LEN; idx += TPB) {
        int e = idx & (E_LEN - 1);
        int k = idx >> 9;
        float2 wv = *(const float2*)(w + e * NCLS + 2 * k);   // even class -> 8B aligned
        s_w[e * WSTR + k] = pk2(wv.x, wv.y);
    }
    __syncthreads();

    // --- Gram prologue: 105 unique pairs, warp-per-pair ---
    {
        const float* wf = (const float*)s_w;   // w[e][c] at float idx e*2*WSTR + c
        for (int p = wid; p < 105; p += WPB) {
            int c1 = 0, rem = p;
            while (rem >= NCLS - c1) { rem -= NCLS - c1; c1++; }
            int c2 = c1 + rem;
            float s = 0.f;
            #pragma unroll
            for (int k = 0; k < 16; k++) {
                int eb = (lane + 32 * k) * 2 * WSTR;
                s = fmaf(wf[eb + c1], wf[eb + c2], s);
            }
            #pragma unroll
            for (int o = 16; o; o >>= 1) s += __shfl_xor_sync(~0u, s, o);
            if (lane == 0) { s_G[c1 * NCLS + c2] = s; s_G[c2 * NCLS + c1] = s; }
        }
    }
    __syncthreads();

    // --- Main loop: warp per sample; lane owns e = lane + 32*j (ALL 8 m) ---
    const int gw = wid * GRID + blockIdx.x;
    float wacc = 0.f;

    for (int s = gw; s < BATCH; s += NWARPS) {
        const float4* px = (const float4*)(x + (size_t)s * ROW);

        // depth-2 software pipeline of the two float4 loads per e-iteration
        float4 a0 = __ldcs(px + lane * 2),        b0 = __ldcs(px + lane * 2 + 1);
        float4 a1 = __ldcs(px + (lane + 32) * 2), b1 = __ldcs(px + (lane + 32) * 2 + 1);

        u64 v[64];                              // flat f = m*8 + cc (cc<7; cc==7 pad)
        #pragma unroll
        for (int f = 0; f < 64; f++) v[f] = 0ull;
        float l1 = 0.f;

        #pragma unroll
        for (int j = 0; j < 16; j++) {
            int jn = (j + 2 < 16) ? (j + 2) : 15;
            float4 a2 = __ldcs(px + (lane + 32 * jn) * 2);
            float4 b2 = __ldcs(px + (lane + 32 * jn) * 2 + 1);
            const int e = lane + 32 * j;

            // 4 vector LDS for the 7 packed class-pairs of this e
            const u64* wp = s_w + e * WSTR;
            ulonglong2 wA = *(const ulonglong2*)(wp);       // cc0, cc1
            ulonglong2 wB = *(const ulonglong2*)(wp + 2);   // cc2, cc3
            ulonglong2 wC = *(const ulonglong2*)(wp + 4);   // cc4, cc5
            u64 w6 = wp[6];                                 // cc6
            u64 ww[7] = { wA.x, wA.y, wB.x, wB.y, wC.x, wC.y, w6 };

            // broadcast each un[e,m] into both f32x2 halves: 56 independent FFMA2
            u64 bm[8] = { bc2(a0.x), bc2(a0.y), bc2(a0.z), bc2(a0.w),
                          bc2(b0.x), bc2(b0.y), bc2(b0.z), bc2(b0.w) };
            #pragma unroll
            for (int cc = 0; cc < 7; cc++) {
                #pragma unroll
                for (int m = 0; m < 8; m++)
                    v[m * 8 + cc] = fma2(bm[m], ww[cc], v[m * 8 + cc]);
            }

            // per-(b,e) variance over 8 m, packed (no cross-lane traffic)
            u64 p01 = pk2(a0.x, a0.y), p23 = pk2(a0.z, a0.w);
            u64 p45 = pk2(b0.x, b0.y), p67 = pk2(b0.z, b0.w);
            u64 S = add2(add2(p01, p23), add2(p45, p67));
            u64 Q = fma2(p01, p01, fma2(p23, p23, fma2(p45, p45, mul2(p67, p67))));
            float se, so, qe, qo;
            up2(se, so, S); up2(qe, qo, Q);
            float s1 = se + so, s2 = qe + qo;
            float u = fmaf(s1 * s1, -0.125f, s2);   // 7*var ; /7 folded into epilogue
            l1 += fabsf(u);

            a0 = a1; b0 = b1; a1 = a2; b1 = b2;
        }

        // full-warp partitioned reduction of the 64 packed partials
        red_stage<32, 16>(v, lane);
        red_stage<16,  8>(v, lane);
        red_stage< 8,  4>(v, lane);
        red_stage< 4,  2>(v, lane);
        red_stage< 2,  1>(v, lane);
        s_red[wid][2 * lane]     = v[0];
        s_red[wid][2 * lane + 1] = v[1];
        __syncwarp();

        // dot[c] = max_m acc[m][c]
        if (lane < NCLS) {
            int cc = lane >> 1, hf = lane & 1;
            const float* rp = (const float*)&s_red[wid][0];
            float mx = rp[(0 * 8 + cc) * 2 + hf];
            #pragma unroll
            for (int m = 1; m < 8; m++) mx = fmaxf(mx, rp[(m * 8 + cc) * 2 + hf]);
            s_dot[wid][lane] = mx;
        }
        int yv = (lane < NCLS) ? __ldg(y + (size_t)s * NCLS + lane) : 0;
        unsigned mask = __ballot_sync(~0u, yv == 1);
        __syncwarp();

        // pairwise softplus + Gram sums, distributed over lanes
        float psum = 0.f, gs = 0.f, ds = 0.f;
        for (int idx = lane; idx < NPAIR; idx += 32) {
            int p = idx / NCLS, n = idx - p * NCLS;
            bool pp = (mask >> p) & 1, pn = (mask >> n) & 1;
            if (pp && !pn) psum += softplus_f(s_dot[wid][n] - s_dot[wid][p]);
            if (pp && pn) { float g = s_G[idx]; gs += g; if (p == n) ds += g; }
        }
        float li = l1;                           // each lane owns distinct e: no overcount
        #pragma unroll
        for (int o = 16; o; o >>= 1) {
            psum += __shfl_xor_sync(~0u, psum, o);
            gs   += __shfl_xor_sync(~0u, gs,   o);
            ds   += __shfl_xor_sync(~0u, ds,   o);
            li   += __shfl_xor_sync(~0u, li,   o);
        }

        if (lane == 0) {
            float npos = (float)__popc(mask);
            float S = psum;
            if ((mask & 0x3FFFu) == 0x3FFFu) {   // nneg == 0 edge case
                S = 0.f;
                for (int c = 0; c < NCLS; c++) S += softplus_f(-s_dot[wid][c]);
            }
            float base = S / npos;
            float tv = (npos > 1.5f) ? (ds - gs / npos) / (npos - 1.f) : 0.f;
            float loss = 2.f * (0.7f * (1.f + tv) * base + 0.3f * (li * (1.0f / 7.0f)));
            wacc += loss;
        }
    }

    // --- block-local then grid reduction (deterministic fixed-order sums) ---
    if (lane == 0) s_wsum[wid] = wacc;
    __syncthreads();
    if (tid == 0) {
        float b = 0.f;
        #pragma unroll
        for (int i = 0; i < WPB; i++) b += s_wsum[i];
        g_block[blockIdx.x] = b;
        __threadfence();
        unsigned t = atomicAdd(&g_count, 1);
        s_last = (t == GRID - 1);
    }
    __syncthreads();
    if (s_last && wid == 0) {
        __threadfence();
        float t = 0.f;
        for (int i = lane; i < GRID; i += 32) {
            float bv; asm volatile("ld.global.cg.f32 %0, [%1];" : "=f"(bv) : "l"(g_block + i));
            t += bv;
        }
        #pragma unroll
        for (int o = 16; o; o >>= 1) t += __shfl_xor_sync(~0u, t, o);
        if (lane == 0) {
            out[0] = t * (1.0f / (float)BATCH);
            g_count = 0;                         // reset for next graph replay
        }
    }
}

extern "C" void kernel_launch(void* const* d_in, const int* in_sizes, int n_in,
                              void* d_out, int out_size) {
    const float* x = nullptr; const int* y = nullptr; const float* w = nullptr;
    for (int i = 0; i < n_in; i++) {
        if      (in_sizes[i] == BATCH * ROW)   x = (const float*)d_in[i];
        else if (in_sizes[i] == BATCH * NCLS)  y = (const int*)d_in[i];
        else if (in_sizes[i] == E_LEN * NCLS)  w = (const float*)d_in[i];
    }
    main_kernel<<<GRID, TPB>>>(x, y, w, (float*)d_out);
}